// round 15
// baseline (speedup 1.0000x reference)
#include <cuda_runtime.h>
#include <cuda_fp16.h>

#define NN 4096

// fp16 complex scratch for the stage-8 intermediate (67 MB).
__device__ __half2 g_scr[(size_t)NN * NN];

// butterfly: (top, bot) -> (top + tw*bot, top - tw*bot), tw = cs + i*sn
static __device__ __forceinline__ void bf(float& tr_, float& ti_,
                                          float& br_, float& bi_,
                                          float cs, float sn) {
    float tr = cs * br_ - sn * bi_;
    float ti = cs * bi_ + sn * br_;
    br_ = tr_ - tr;
    bi_ = ti_ - ti;
    tr_ += tr;
    ti_ += ti;
}

// twiddle-free butterfly (r = 0, bit-identical to general path at k = 0)
static __device__ __forceinline__ void bf0(float& tr_, float& ti_,
                                           float& br_, float& bi_) {
    const float tr = br_, ti = bi_;
    br_ = tr_ - tr;
    bi_ = ti_ - ti;
    tr_ += tr;
    ti_ += ti;
}

// phase = (-2*pi) * (k/4096) * W[k,d], fp32, reference rounding order
static __device__ __forceinline__ float phase_of(int k, float w) {
    return (-6.2831855f) * ((float)k * (1.0f / 4096.0f)) * w;
}

// ---------------------------------------------------------------------------
// Kernel A (R14 + g-loop): permutation + stages step=2..256.
// CTA = 16-column tile x 4 row-groups (looped). Per g: 256 threads,
// m = tx>>4, c = tx&15. W addresses are g-invariant -> L1 serves them after
// the first g iteration, cutting W L2 bytes ~4x.
// ---------------------------------------------------------------------------
__global__ __launch_bounds__(256) void fftA(const float* __restrict__ x,
                                            const float* __restrict__ W) {
    __shared__ float2 sm[256 * 16];   // 32 KB exchange
    const int tx = threadIdx.x;
    const int m  = tx >> 4;           // 0..15
    const int c  = tx & 15;           // 0..15
    const int d  = blockIdx.x * 16 + c;

    for (int gi = 0; gi < 4; ++gi) {
        const int g   = blockIdx.y * 4 + gi;  // 0..15
        const int gin = g ^ 8;                // i^2048 flips group bit 3

        float re[16], im[16];

        // Load 16 contiguous rows of column d from the permuted source group.
        {
            const float* xp = x + (size_t)(gin * 256 + m * 16) * NN + d;
            #pragma unroll
            for (int i = 0; i < 16; ++i) {
                re[i] = xp[(size_t)i * NN];
                im[i] = 0.0f;
            }
        }

        // Round 1: stages step = 2,4,8,16 (r = 0 specialized).
        #pragma unroll
        for (int s = 1; s <= 4; ++s) {
            const int step = 1 << s, half = step >> 1;
            #pragma unroll
            for (int bb = 0; bb < 16; bb += step)
                bf0(re[bb], im[bb], re[bb + half], im[bb + half]);
            #pragma unroll
            for (int r = 1; r < half; ++r) {
                const int k = r << (12 - s);
                float sn, cs;
                __sincosf(phase_of(k, W[(size_t)k * NN + d]), &sn, &cs);
                #pragma unroll
                for (int bb = 0; bb < 16; bb += step) {
                    const int j = bb + r;
                    bf(re[j], im[j], re[j + half], im[j + half], cs, sn);
                }
            }
        }

        // Exchange: write rows m*16+i, read rows m+16j.
        #pragma unroll
        for (int i = 0; i < 16; ++i)
            sm[(m * 16 + i) * 16 + c] = make_float2(re[i], im[i]);
        __syncthreads();
        #pragma unroll
        for (int j = 0; j < 16; ++j) {
            float2 v = sm[(m + 16 * j) * 16 + c];
            re[j] = v.x;
            im[j] = v.y;
        }

        // Round 2: stages step = 32,64,128,256 (local row l = m + 16j).
        #pragma unroll
        for (int s = 5; s <= 8; ++s) {
            const int jstep = 1 << (s - 4), jhalf = jstep >> 1;
            #pragma unroll
            for (int rr = 0; rr < jhalf; ++rr) {
                const int k = (m + 16 * rr) << (12 - s);
                float sn, cs;
                __sincosf(phase_of(k, W[(size_t)k * NN + d]), &sn, &cs);
                #pragma unroll
                for (int jb = 0; jb < 16; jb += jstep) {
                    const int j = jb + rr;
                    bf(re[j], im[j], re[j + jhalf], im[j + jhalf], cs, sn);
                }
            }
        }

        // Store rows g*256 + m + 16j as packed half2.
        {
            __half2* sp = g_scr + (size_t)(g * 256 + m) * NN + d;
            #pragma unroll
            for (int j = 0; j < 16; ++j)
                sp[(size_t)(16 * j) * NN] = __floats2half2_rn(re[j], im[j]);
        }

        // sm is rewritten next iteration; reads above must complete first.
        __syncthreads();
    }
}

// ---------------------------------------------------------------------------
// Kernel B (R8 form + front-batched W loads): stages step = 512..4096.
// Row i = a*256 + b; 16-point network over a for fixed b. All 15 W loads are
// issued together with the 16 scratch loads (MLP ~31) before any butterfly.
// ---------------------------------------------------------------------------
__global__ __launch_bounds__(256) void fftB(const float* __restrict__ W,
                                            float* __restrict__ out) {
    const int d = blockIdx.x * 256 + threadIdx.x;  // grid.x = 16
    const int b = blockIdx.y;                      // 0..255

    float re[16], im[16];
    {
        const __half2* sp = g_scr + (size_t)b * NN + d;
        #pragma unroll
        for (int a = 0; a < 16; ++a) {
            float2 v = __half22float2(sp[(size_t)(a * 256) * NN]);
            re[a] = v.x;
            im[a] = v.y;
        }
    }

    // Front-batched W loads: base = (1<<(s-9))-1 + rr, k = (256*rr+b)<<(12-s).
    float wv[15];
    #pragma unroll
    for (int s = 9; s <= 12; ++s) {
        const int base = (1 << (s - 9)) - 1;
        #pragma unroll
        for (int rr = 0; rr < (1 << (s - 9)); ++rr) {
            const int k = (256 * rr + b) << (12 - s);
            wv[base + rr] = W[(size_t)k * NN + d];
        }
    }

    #pragma unroll
    for (int s = 9; s <= 12; ++s) {
        const int astep = 1 << (s - 8), ahalf = astep >> 1;
        const int base = ahalf - 1;
        #pragma unroll
        for (int rr = 0; rr < ahalf; ++rr) {
            const int k = (256 * rr + b) << (12 - s);
            float sn, cs;
            __sincosf(phase_of(k, wv[base + rr]), &sn, &cs);
            #pragma unroll
            for (int ab = 0; ab < 16; ab += astep) {
                const int a = ab + rr;
                bf(re[a], im[a], re[a + ahalf], im[a + ahalf], cs, sn);
            }
        }
    }

    {
        float* op = out + (size_t)b * NN + d;
        #pragma unroll
        for (int a = 0; a < 16; ++a)
            op[(size_t)(a * 256) * NN] = re[a];
    }
}

extern "C" void kernel_launch(void* const* d_in, const int* in_sizes, int n_in,
                              void* d_out, int out_size) {
    if (n_in < 2 || d_in == nullptr || d_out == nullptr || in_sizes == nullptr)
        return;
    if (d_in[0] == nullptr || d_in[1] == nullptr)
        return;
    if (in_sizes[0] < NN * NN || in_sizes[1] < NN * NN)
        return;
    if (out_size < NN * NN)
        return;

    const float* x = (const float*)d_in[0]; // (4096,4096) float32
    const float* W = (const float*)d_in[1]; // (4096,4096) float32 weights
    float* out = (float*)d_out;             // (4096,4096) float32 = Re(FFT)

    dim3 gA(NN / 16, 4);    // 256 column tiles x 4 CTAs, each looping 4 groups
    fftA<<<gA, 256>>>(x, W);

    dim3 gB(NN / 256, 256); // 16 column tiles x 256 b-values
    fftB<<<gB, 256>>>(W, out);
}

// round 16
// speedup vs baseline: 1.1648x; 1.1648x over previous
#include <cuda_runtime.h>
#include <cuda_fp16.h>

#define NN 4096

// fp16 complex scratch for the stage-8 intermediate (67 MB).
__device__ __half2 g_scr[(size_t)NN * NN];

// butterfly: (top, bot) -> (top + tw*bot, top - tw*bot), tw = cs + i*sn
static __device__ __forceinline__ void bf(float& tr_, float& ti_,
                                          float& br_, float& bi_,
                                          float cs, float sn) {
    float tr = cs * br_ - sn * bi_;
    float ti = cs * bi_ + sn * br_;
    br_ = tr_ - tr;
    bi_ = ti_ - ti;
    tr_ += tr;
    ti_ += ti;
}

// twiddle-free butterfly (r = 0, bit-identical to general path at k = 0)
static __device__ __forceinline__ void bf0(float& tr_, float& ti_,
                                           float& br_, float& bi_) {
    const float tr = br_, ti = bi_;
    br_ = tr_ - tr;
    bi_ = ti_ - ti;
    tr_ += tr;
    ti_ += ti;
}

// phase = (-2*pi) * (k/4096) * W[k,d], fp32, reference rounding order
static __device__ __forceinline__ float phase_of(int k, float w) {
    return (-6.2831855f) * ((float)k * (1.0f / 4096.0f)) * w;
}

// ---------------------------------------------------------------------------
// Kernel A (R14 exact — best measured fftA, 34.8us): permutation + stages
// step=2..256. CTA = 256-row group x 16-column tile, 256 threads.
// Round 1 r=0 butterflies specialized (no twiddle/W-load/sincos).
// ---------------------------------------------------------------------------
__global__ __launch_bounds__(256) void fftA(const float* __restrict__ x,
                                            const float* __restrict__ W) {
    __shared__ float2 sm[256 * 16];   // 32 KB exchange
    const int tx = threadIdx.x;
    const int m  = tx >> 4;           // 0..15
    const int c  = tx & 15;           // 0..15
    const int d  = blockIdx.x * 16 + c;
    const int g  = blockIdx.y;        // 0..15
    const int gin = g ^ 8;            // i^2048 flips group bit 3

    float re[16], im[16];

    // Load 16 contiguous rows of column d from the permuted source group.
    {
        const float* xp = x + (size_t)(gin * 256 + m * 16) * NN + d;
        #pragma unroll
        for (int i = 0; i < 16; ++i) {
            re[i] = xp[(size_t)i * NN];
            im[i] = 0.0f;
        }
    }

    // Round 1: stages step = 2,4,8,16 (r = 0 specialized).
    #pragma unroll
    for (int s = 1; s <= 4; ++s) {
        const int step = 1 << s, half = step >> 1;
        #pragma unroll
        for (int bb = 0; bb < 16; bb += step)
            bf0(re[bb], im[bb], re[bb + half], im[bb + half]);
        #pragma unroll
        for (int r = 1; r < half; ++r) {
            const int k = r << (12 - s);
            float sn, cs;
            __sincosf(phase_of(k, W[(size_t)k * NN + d]), &sn, &cs);
            #pragma unroll
            for (int bb = 0; bb < 16; bb += step) {
                const int j = bb + r;
                bf(re[j], im[j], re[j + half], im[j + half], cs, sn);
            }
        }
    }

    // Exchange: write rows m*16+i, read rows m+16j.
    #pragma unroll
    for (int i = 0; i < 16; ++i)
        sm[(m * 16 + i) * 16 + c] = make_float2(re[i], im[i]);
    __syncthreads();
    #pragma unroll
    for (int j = 0; j < 16; ++j) {
        float2 v = sm[(m + 16 * j) * 16 + c];
        re[j] = v.x;
        im[j] = v.y;
    }

    // Round 2: stages step = 32,64,128,256 (local row l = m + 16j).
    #pragma unroll
    for (int s = 5; s <= 8; ++s) {
        const int jstep = 1 << (s - 4), jhalf = jstep >> 1;
        #pragma unroll
        for (int rr = 0; rr < jhalf; ++rr) {
            const int k = (m + 16 * rr) << (12 - s);
            float sn, cs;
            __sincosf(phase_of(k, W[(size_t)k * NN + d]), &sn, &cs);
            #pragma unroll
            for (int jb = 0; jb < 16; jb += jstep) {
                const int j = jb + rr;
                bf(re[j], im[j], re[j + jhalf], im[j + jhalf], cs, sn);
            }
        }
    }

    // Store rows g*256 + m + 16j as packed half2.
    {
        __half2* sp = g_scr + (size_t)(g * 256 + m) * NN + d;
        #pragma unroll
        for (int j = 0; j < 16; ++j)
            sp[(size_t)(16 * j) * NN] = __floats2half2_rn(re[j], im[j]);
    }
}

// ---------------------------------------------------------------------------
// Kernel B (R15 exact — best measured fftB, 27.8us): stages step = 512..4096.
// Row i = a*256 + b; 16-point network over a for fixed b. All 15 W loads
// front-batched with the 16 scratch loads (MLP ~31).
// ---------------------------------------------------------------------------
__global__ __launch_bounds__(256) void fftB(const float* __restrict__ W,
                                            float* __restrict__ out) {
    const int d = blockIdx.x * 256 + threadIdx.x;  // grid.x = 16
    const int b = blockIdx.y;                      // 0..255

    float re[16], im[16];
    {
        const __half2* sp = g_scr + (size_t)b * NN + d;
        #pragma unroll
        for (int a = 0; a < 16; ++a) {
            float2 v = __half22float2(sp[(size_t)(a * 256) * NN]);
            re[a] = v.x;
            im[a] = v.y;
        }
    }

    // Front-batched W loads: base = (1<<(s-9))-1 + rr, k = (256*rr+b)<<(12-s).
    float wv[15];
    #pragma unroll
    for (int s = 9; s <= 12; ++s) {
        const int base = (1 << (s - 9)) - 1;
        #pragma unroll
        for (int rr = 0; rr < (1 << (s - 9)); ++rr) {
            const int k = (256 * rr + b) << (12 - s);
            wv[base + rr] = W[(size_t)k * NN + d];
        }
    }

    #pragma unroll
    for (int s = 9; s <= 12; ++s) {
        const int astep = 1 << (s - 8), ahalf = astep >> 1;
        const int base = ahalf - 1;
        #pragma unroll
        for (int rr = 0; rr < ahalf; ++rr) {
            const int k = (256 * rr + b) << (12 - s);
            float sn, cs;
            __sincosf(phase_of(k, wv[base + rr]), &sn, &cs);
            #pragma unroll
            for (int ab = 0; ab < 16; ab += astep) {
                const int a = ab + rr;
                bf(re[a], im[a], re[a + ahalf], im[a + ahalf], cs, sn);
            }
        }
    }

    {
        float* op = out + (size_t)b * NN + d;
        #pragma unroll
        for (int a = 0; a < 16; ++a)
            op[(size_t)(a * 256) * NN] = re[a];
    }
}

extern "C" void kernel_launch(void* const* d_in, const int* in_sizes, int n_in,
                              void* d_out, int out_size) {
    if (n_in < 2 || d_in == nullptr || d_out == nullptr || in_sizes == nullptr)
        return;
    if (d_in[0] == nullptr || d_in[1] == nullptr)
        return;
    if (in_sizes[0] < NN * NN || in_sizes[1] < NN * NN)
        return;
    if (out_size < NN * NN)
        return;

    const float* x = (const float*)d_in[0]; // (4096,4096) float32
    const float* W = (const float*)d_in[1]; // (4096,4096) float32 weights
    float* out = (float*)d_out;             // (4096,4096) float32 = Re(FFT)

    dim3 gA(NN / 16, 16);   // 256 column tiles x 16 row groups, 256 thr
    fftA<<<gA, 256>>>(x, W);

    dim3 gB(NN / 256, 256); // 16 column tiles x 256 b-values
    fftB<<<gB, 256>>>(W, out);
}